// round 7
// baseline (speedup 1.0000x reference)
#include <cuda_runtime.h>
#include <cstdint>

#define BNUM 4
#define HS 64
#define WS 64
#define HU 512
#define WU 512
#define CORI 90
#define CMNT 180
#define COFF 8
#define KCAND 1024
#define NCELL (HS*WS)       // 4096
#define NPIX (HU*WU)        // 262144
#define PPAD 24
#define PDIM (512+PPAD)     // 536 padded extent

// output layout: minut [4,1024,4] | keep [4,1024] | enh_vis | mask_up*255 | ori_field
#define MINUT_OFF 0
#define KEEP_OFF  16384
#define ENH_OFF   20480
#define MASK_OFF  1069056
#define ORI_OFF   2117632

__device__ float g_mask[BNUM*NCELL];
__device__ float g_pA[BNUM*PDIM*512];   // padded run-8 scratch
__device__ float g_tA[BNUM*NPIX];
__device__ float g_tB[BNUM*NPIX];
__device__ float g_maskup[BNUM*NPIX];
__device__ unsigned g_emin[BNUM];
__device__ unsigned g_emax[BNUM];

__device__ __forceinline__ unsigned f2ord(float f){
    unsigned u=__float_as_uint(f);
    return (u & 0x80000000u) ? ~u : (u | 0x80000000u);
}
__device__ __forceinline__ float ord2f(unsigned u){
    u = (u & 0x80000000u) ? (u & 0x7fffffffu) : ~u;
    return __uint_as_float(u);
}

// ---------- fused 5x5 opening on [B,64,64] + minmax init (R1-class) ----------
__global__ void __launch_bounds__(1024) opening_small(const float* __restrict__ seg){
    __shared__ float s0[NCELL];
    __shared__ float s1[NCELL];
    int b=blockIdx.x, tid=threadIdx.x;
    if(b==0 && tid<BNUM){ g_emin[tid]=0xFFFFFFFFu; g_emax[tid]=0u; }
    const float* sg=seg+(size_t)b*NCELL;
    for(int t=tid;t<NCELL;t+=1024) s0[t]=rintf(sg[t]);
    __syncthreads();
    for(int t=tid;t<NCELL;t+=1024){
        int r=t>>6, c=t&63;
        int y0=max(r-2,0), y1=min(r+2,HS-1), x0=max(c-2,0), x1=min(c+2,WS-1);
        float m=1e30f;
        for(int y=y0;y<=y1;y++)
            for(int x=x0;x<=x1;x++)
                m=fminf(m,s0[(y<<6)+x]);
        s1[t]=m;
    }
    __syncthreads();
    for(int t=tid;t<NCELL;t+=1024){
        int r=t>>6, c=t&63;
        int y0=max(r-2,0), y1=min(r+2,HS-1), x0=max(c-2,0), x1=min(c+2,WS-1);
        float m=-1e30f;
        for(int y=y0;y<=y1;y++)
            for(int x=x0;x<=x1;x++)
                m=fmaxf(m,s1[(y<<6)+x]);
        g_mask[(size_t)b*NCELL+t]=m;
    }
}

// ======== 40-wide separable opening, decomposed as run-8 + 5-tap combine =======
// All kernels: per-pixel independent, 256-thread blocks, no shared/barriers.

// vertical run-8 into padded buffer: out[b][r][x], r in [0,PDIM), y=r-PPAD in [-24,511]
// P[y] = op over rows [y, y+7] (rows outside [0,511] -> neutral)
template<bool MN, bool RND>
__global__ void __launch_bounds__(256) v8(const float* __restrict__ in, float* __restrict__ outp){
    int i=blockIdx.x*256+threadIdx.x;
    if(i>=BNUM*PDIM*512) return;
    int b=i/(PDIM*512); int rem=i%(PDIM*512); int r=rem>>9; int x=rem&511;
    int y=r-PPAD;
    const float* s=in+(size_t)b*NPIX+x;
    const float NEU=MN?1e30f:-1e30f;
    float m=NEU;
    #pragma unroll
    for(int k=0;k<8;k++){
        int yy=y+k;
        float v=(yy>=0 && yy<HU)? s[(size_t)yy*WU] : NEU;
        if(RND) v=rintf(v);
        m=MN?fminf(m,v):fmaxf(m,v);
    }
    outp[i]=m;
}
// vertical 5-tap combine: win40[y] = op over P[y-19+8k], k=0..4
template<bool MN>
__global__ void __launch_bounds__(256) v5(const float* __restrict__ inp, float* __restrict__ out){
    int i=blockIdx.x*256+threadIdx.x;
    if(i>=BNUM*NPIX) return;
    int b=i/NPIX; int rem=i%NPIX; int y=rem>>9; int x=rem&511;
    const float* P=inp+(size_t)b*PDIM*512+x;
    const float NEU=MN?1e30f:-1e30f;
    float m=NEU;
    #pragma unroll
    for(int k=0;k<5;k++){
        int p=y-19+8*k;
        float v=(p<=HU-1)? P[(size_t)(p+PPAD)*WU] : NEU;
        m=MN?fminf(m,v):fmaxf(m,v);
    }
    out[i]=m;
}
// horizontal run-8 into padded rows: out[b][row][c], c in [0,PDIM), x=c-PPAD
template<bool MN>
__global__ void __launch_bounds__(256) h8(const float* __restrict__ in, float* __restrict__ outp){
    int i=blockIdx.x*256+threadIdx.x;
    if(i>=BNUM*512*PDIM) return;
    int b=i/(512*PDIM); int rem=i%(512*PDIM); int row=rem/PDIM; int c=rem%PDIM;
    int x=c-PPAD;
    const float* s=in+((size_t)b*HU+row)*WU;
    const float NEU=MN?1e30f:-1e30f;
    float m=NEU;
    #pragma unroll
    for(int k=0;k<8;k++){
        int xx=x+k;
        float v=(xx>=0 && xx<WU)? s[xx] : NEU;
        m=MN?fminf(m,v):fmaxf(m,v);
    }
    outp[i]=m;
}
// horizontal 5-tap combine; FUSED variant also writes mask*255 and enh min/max
template<bool MN, bool FUSED>
__global__ void __launch_bounds__(256) h5(const float* __restrict__ inp, float* __restrict__ out,
                                          const float* __restrict__ enh, float* __restrict__ outg){
    int i=blockIdx.x*256+threadIdx.x;
    if(i>=BNUM*NPIX) return;
    int b=i/NPIX; int rem=i%NPIX; int row=rem>>9; int x=rem&511;
    const float* P=inp+((size_t)b*HU+row)*PDIM;
    const float NEU=MN?1e30f:-1e30f;
    float m=NEU;
    #pragma unroll
    for(int k=0;k<5;k++){
        int p=x-19+8*k;
        float v=(p<=WU-1)? P[p+PPAD] : NEU;
        m=MN?fminf(m,v):fmaxf(m,v);
    }
    out[i]=m;
    if(FUSED){
        outg[MASK_OFF+i]=m*255.0f;
        float ev=enh[i]*m;
        float mn=ev, mx=ev;
        #pragma unroll
        for(int o=16;o;o>>=1){
            mn=fminf(mn,__shfl_xor_sync(0xFFFFFFFFu,mn,o));
            mx=fmaxf(mx,__shfl_xor_sync(0xFFFFFFFFu,mx,o));
        }
        if((threadIdx.x&31)==0){
            atomicMin(&g_emin[b], f2ord(mn));
            atomicMax(&g_emax[b], f2ord(mx));
        }
    }
}

// ---------- detect: top-k + NMS, one block per batch (R1-proven) ----------
__global__ void __launch_bounds__(1024) detect_nms(
    const float* __restrict__ mscore, const float* __restrict__ mori,
    const float* __restrict__ mxo,    const float* __restrict__ myo,
    float* __restrict__ out)
{
    int b=blockIdx.x, tid=threadIdx.x;
    __shared__ unsigned long long keys[4096];   // 32KB
    __shared__ int s_nv;
    float* sx=(float*)(keys+1024);
    float* sy=(float*)(keys+1536);
    float* sa=(float*)(keys+2048);
    unsigned char* skeep=(unsigned char*)(keys+2560);

    const float* sc=mscore+(size_t)b*NCELL;
    const float* mk=g_mask +(size_t)b*NCELL;

    bool anyv=false;
    for(int t=tid;t<NCELL;t+=1024){
        float v=sc[t]*mk[t];
        bool val = v>0.5f;
        anyv |= val;
        float mv = val ? v : -1.0f;
        keys[t] = ((unsigned long long)(~f2ord(mv))<<32) | (unsigned)t;
    }
    if(__syncthreads_count(anyv)==0){
        float* om=out + MINUT_OFF + (size_t)b*KCAND*4 + (size_t)tid*4;
        om[0]=0.0f; om[1]=0.0f; om[2]=0.0f; om[3]=0.0f;
        out[KEEP_OFF + (size_t)b*KCAND + tid]=0.0f;
        return;
    }
    for(int k=2;k<=4096;k<<=1){
        for(int j=k>>1;j>0;j>>=1){
            for(int i=tid;i<4096;i+=1024){
                int ixj=i^j;
                if(ixj>i){
                    unsigned long long a=keys[i], c=keys[ixj];
                    bool up=((i&k)==0);
                    if((a>c)==up){ keys[i]=c; keys[ixj]=a; }
                }
            }
            __syncthreads();
        }
    }
    unsigned long long key=keys[tid];
    int idx=(int)(key & 0xFFFFFFFFull);
    float mv = ord2f(~(unsigned)(key>>32));
    bool valid = mv>0.5f;
    float score = valid ? mv : 0.0f;
    float xc=0.0f, yc=0.0f, ang=0.0f;
    if(valid){
        int r=idx>>6, c=idx&63;
        const float* o=mori+(size_t)b*CMNT*NCELL+idx;
        int ai=0; float bv=o[0];
        for(int ch=1;ch<CMNT;ch++){ float v=o[(size_t)ch*NCELL]; if(v>bv){bv=v;ai=ch;} }
        const float* xo=mxo+(size_t)b*COFF*NCELL+idx;
        int xi=0; float bx=xo[0];
        for(int ch=1;ch<COFF;ch++){ float v=xo[(size_t)ch*NCELL]; if(v>bx){bx=v;xi=ch;} }
        const float* yo=myo+(size_t)b*COFF*NCELL+idx;
        int yi=0; float by=yo[0];
        for(int ch=1;ch<COFF;ch++){ float v=yo[(size_t)ch*NCELL]; if(v>by){by=v;yi=ch;} }
        ang=((float)ai*2.0f-89.0f)*0.017453292519943295f;
        xc=(float)c*8.0f+(float)xi;
        yc=(float)r*8.0f+(float)yi;
    }
    if(tid==0) s_nv=0;
    __syncthreads();
    sx[tid]=xc; sy[tid]=yc; sa[tid]=ang; skeep[tid]=valid?1:0;
    atomicMax(&s_nv, valid?(tid+1):0);
    __syncthreads();
    int nv=s_nv;
    for(int i=0;i<nv;i++){
        if(skeep[i] && tid>i && skeep[tid]){
            float dx=sx[tid]-sx[i], dy=sy[tid]-sy[i];
            float d=sqrtf(dx*dx+dy*dy);
            float da=fabsf(sa[tid]-sa[i]);
            da=fminf(da, 6.2831853071795864f-da);
            if(d<16.0f && da<0.52359877559829887f) skeep[tid]=0;
        }
        __syncthreads();
    }
    float kf = skeep[tid]?1.0f:0.0f;
    float* om=out + MINUT_OFF + (size_t)b*KCAND*4 + (size_t)tid*4;
    om[0]=kf*xc; om[1]=kf*yc; om[2]=kf*ang; om[3]=kf*score;
    out[KEEP_OFF + (size_t)b*KCAND + tid]=kf;
}

// ---------- finalize: enh_vis + ori_field (mask-predicated) ----------
__global__ void __launch_bounds__(256) finalize(const float* __restrict__ enh,
                         const float* __restrict__ oriup, float* __restrict__ out){
    int i=blockIdx.x*blockDim.x+threadIdx.x;
    if(i>=BNUM*NPIX) return;
    int b=i/NPIX, p=i%NPIX;
    float m=g_maskup[i];
    float emin=ord2f(g_emin[b]);
    float emax=ord2f(g_emax[b]);
    float e=enh[i]*m;
    out[ENH_OFF+i]=(e-emin)/(emax-emin+1e-8f)*255.0f;
    float of=0.0f;
    if(m!=0.0f){
        const float* o=oriup+(size_t)b*CORI*NPIX+p;
        int ai=0; float bv=o[0];
        for(int ch=1;ch<CORI;ch++){ float v=o[(size_t)ch*NPIX]; if(v>bv){bv=v;ai=ch;} }
        of=((float)ai*2.0f-90.0f)*0.017453292519943295f*m;
    }
    out[ORI_OFF+i]=of;
}

extern "C" void kernel_launch(void* const* d_in, const int* in_sizes, int n_in,
                              void* d_out, int out_size){
    const float* seg    =(const float*)d_in[0];
    const float* segup  =(const float*)d_in[1];
    const float* oriup  =(const float*)d_in[2];
    const float* enh    =(const float*)d_in[3];
    const float* mscore =(const float*)d_in[4];
    const float* mori   =(const float*)d_in[5];
    const float* mxo    =(const float*)d_in[6];
    const float* myo    =(const float*)d_in[7];
    float* out=(float*)d_out;

    int nPad=(BNUM*PDIM*512+255)/256;   // 4288 blocks
    int nBig=(BNUM*NPIX+255)/256;       // 4096 blocks

    opening_small<<<BNUM,1024>>>(seg);                        // + minmax init
    // erosion: vmin then hmin ; dilation: vmax then hmax — each as run8 + 5tap
    v8<true ,true ><<<nPad,256>>>(segup, g_pA);
    v5<true ><<<nBig,256>>>(g_pA, g_tA);
    h8<true ><<<nPad,256>>>(g_tA, g_pA);
    h5<true ,false><<<nBig,256>>>(g_pA, g_tB, nullptr, nullptr);
    v8<false,false><<<nPad,256>>>(g_tB, g_pA);
    v5<false><<<nBig,256>>>(g_pA, g_tA);
    h8<false><<<nPad,256>>>(g_tA, g_pA);
    h5<false,true ><<<nBig,256>>>(g_pA, g_maskup, enh, out);  // + mask out + enh minmax

    detect_nms<<<BNUM,1024>>>(mscore, mori, mxo, myo, out);
    finalize<<<nBig,256>>>(enh, oriup, out);
}

// round 8
// speedup vs baseline: 10.5830x; 10.5830x over previous
#include <cuda_runtime.h>
#include <cstdint>

#define BNUM 4
#define HS 64
#define WS 64
#define HU 512
#define WU 512
#define CORI 90
#define CMNT 180
#define COFF 8
#define KCAND 1024
#define NCELL (HS*WS)       // 4096
#define NPIX (HU*WU)        // 262144

// output layout (concatenated flattened returns):
// minut [4,1024,4] | keep [4,1024] | enh_vis [4,512,512] | mask_up*255 | ori_field
#define MINUT_OFF 0
#define KEEP_OFF  16384
#define ENH_OFF   20480
#define MASK_OFF  1069056
#define ORI_OFF   2117632

// -------- device scratch (no allocations allowed) --------
__device__ float g_mask[BNUM*NCELL];
__device__ float g_er[BNUM*NCELL];
__device__ float g_tA[BNUM*NPIX];
__device__ float g_tB[BNUM*NPIX];
__device__ float g_maskup[BNUM*NPIX];
__device__ unsigned g_emin[BNUM];
__device__ unsigned g_emax[BNUM];

// -------- helpers --------
__device__ __forceinline__ unsigned f2ord(float f){
    unsigned u=__float_as_uint(f);
    return (u & 0x80000000u) ? ~u : (u | 0x80000000u);   // ascending order-preserving
}
__device__ __forceinline__ float ord2f(unsigned u){
    u = (u & 0x80000000u) ? (u & 0x7fffffffu) : ~u;
    return __uint_as_float(u);
}

// -------- small 5x5 opening on [B,64,64] (+ minmax init folded in) --------
__global__ void small_erode(const float* __restrict__ seg){
    int i=blockIdx.x*blockDim.x+threadIdx.x;
    if(i<BNUM){ g_emin[i]=0xFFFFFFFFu; g_emax[i]=0u; }
    if(i>=BNUM*NCELL) return;
    int b=i/NCELL, cell=i%NCELL, r=cell/WS, c=cell%WS;
    const float* s=seg+(size_t)b*NCELL;
    int y0=r-2<0?0:r-2, y1=r+2>HS-1?HS-1:r+2;
    int x0=c-2<0?0:c-2, x1=c+2>WS-1?WS-1:c+2;
    float m=1e30f;
    for(int y=y0;y<=y1;y++)
        for(int x=x0;x<=x1;x++)
            m=fminf(m, rintf(s[y*WS+x]));
    g_er[i]=m;
}
__global__ void small_dilate(){
    int i=blockIdx.x*blockDim.x+threadIdx.x;
    if(i>=BNUM*NCELL) return;
    int b=i/NCELL, cell=i%NCELL, r=cell/WS, c=cell%WS;
    const float* s=g_er+(size_t)b*NCELL;
    int y0=r-2<0?0:r-2, y1=r+2>HS-1?HS-1:r+2;
    int x0=c-2<0?0:c-2, x1=c+2>WS-1?WS-1:c+2;
    float m=-1e30f;
    for(int y=y0;y<=y1;y++)
        for(int x=x0;x<=x1;x++)
            m=fmaxf(m, s[y*WS+x]);
    g_mask[i]=m;
}

// -------- 40-wide separable opening on [B,512,512] ; window [i-19, i+20] --------
__device__ __forceinline__ float poolV(const float* s, int y, int x, bool isMin, bool doRound){
    int a0=y-19; if(a0<0)a0=0;
    int a1=y+20; if(a1>HU-1)a1=HU-1;
    float m = isMin?1e30f:-1e30f;
    for(int yy=a0;yy<=a1;yy++){
        float v=s[yy*WU+x];
        if(doRound)v=rintf(v);
        m = isMin?fminf(m,v):fmaxf(m,v);
    }
    return m;
}
__device__ __forceinline__ float poolH(const float* s, int y, int x, bool isMin){
    int a0=x-19; if(a0<0)a0=0;
    int a1=x+20; if(a1>WU-1)a1=WU-1;
    const float* row=s+(size_t)y*WU;
    float m = isMin?1e30f:-1e30f;
    for(int xx=a0;xx<=a1;xx++){
        float v=row[xx];
        m = isMin?fminf(m,v):fmaxf(m,v);
    }
    return m;
}
__global__ void up1_vmin(const float* __restrict__ segup){
    int i=blockIdx.x*blockDim.x+threadIdx.x; if(i>=BNUM*NPIX)return;
    int b=i/NPIX, p=i%NPIX;
    g_tA[i]=poolV(segup+(size_t)b*NPIX, p/WU, p%WU, true, true);
}
__global__ void up2_hmin(){
    int i=blockIdx.x*blockDim.x+threadIdx.x; if(i>=BNUM*NPIX)return;
    int b=i/NPIX, p=i%NPIX;
    g_tB[i]=poolH(g_tA+(size_t)b*NPIX, p/WU, p%WU, true);
}
__global__ void up3_vmax(){
    int i=blockIdx.x*blockDim.x+threadIdx.x; if(i>=BNUM*NPIX)return;
    int b=i/NPIX, p=i%NPIX;
    g_tA[i]=poolV(g_tB+(size_t)b*NPIX, p/WU, p%WU, false, false);
}
__global__ void up4_hmax(){
    int i=blockIdx.x*blockDim.x+threadIdx.x; if(i>=BNUM*NPIX)return;
    int b=i/NPIX, p=i%NPIX;
    g_maskup[i]=poolH(g_tA+(size_t)b*NPIX, p/WU, p%WU, false);
}

// -------- enhanced min/max per batch --------
__global__ void enh_minmax(const float* __restrict__ enh){
    int b=blockIdx.y;
    const float* e=enh+(size_t)b*NPIX;
    const float* m=g_maskup+(size_t)b*NPIX;
    float mn=1e30f, mx=-1e30f;
    for(int p=blockIdx.x*blockDim.x+threadIdx.x; p<NPIX; p+=gridDim.x*blockDim.x){
        float v=e[p]*m[p];
        mn=fminf(mn,v); mx=fmaxf(mx,v);
    }
    for(int o=16;o;o>>=1){
        mn=fminf(mn,__shfl_down_sync(0xFFFFFFFFu,mn,o));
        mx=fmaxf(mx,__shfl_down_sync(0xFFFFFFFFu,mx,o));
    }
    __shared__ float smn[8], smx[8];
    int lane=threadIdx.x&31, w=threadIdx.x>>5;
    if(lane==0){ smn[w]=mn; smx[w]=mx; }
    __syncthreads();
    if(threadIdx.x==0){
        int nw=blockDim.x>>5;
        for(int i=1;i<nw;i++){ mn=fminf(mn,smn[i]); mx=fmaxf(mx,smx[i]); }
        atomicMin(&g_emin[b], f2ord(mn));
        atomicMax(&g_emax[b], f2ord(mx));
    }
}

// -------- detect (top-k + NMS), one block per batch --------
__global__ void __launch_bounds__(1024) detect_nms(
    const float* __restrict__ mscore, const float* __restrict__ mori,
    const float* __restrict__ mxo,    const float* __restrict__ myo,
    float* __restrict__ out)
{
    int b=blockIdx.x, tid=threadIdx.x;
    __shared__ unsigned long long keys[4096];   // 32KB
    __shared__ int s_nv;
    // alias scratch into the tail of keys (only keys[0..1023] live after sort read)
    float* sx=(float*)(keys+1024);
    float* sy=(float*)(keys+1536);
    float* sa=(float*)(keys+2048);
    unsigned char* skeep=(unsigned char*)(keys+2560);

    const float* sc=mscore+(size_t)b*NCELL;
    const float* mk=g_mask +(size_t)b*NCELL;

    bool anyv=false;
    for(int t=tid;t<NCELL;t+=1024){
        float v=sc[t]*mk[t];
        bool val = v>0.5f;
        anyv |= val;
        float mv = val ? v : -1.0f;
        // ascending sort of key == descending masked score, ties -> smaller idx first
        keys[t] = ((unsigned long long)(~f2ord(mv))<<32) | (unsigned)t;
    }
    if(__syncthreads_count(anyv)==0){
        // fast path: no candidates anywhere -> all outputs zero
        float* om=out + MINUT_OFF + (size_t)b*KCAND*4 + (size_t)tid*4;
        om[0]=0.0f; om[1]=0.0f; om[2]=0.0f; om[3]=0.0f;
        out[KEEP_OFF + (size_t)b*KCAND + tid]=0.0f;
        return;
    }

    // bitonic sort 4096 keys ascending
    for(int k=2;k<=4096;k<<=1){
        for(int j=k>>1;j>0;j>>=1){
            for(int i=tid;i<4096;i+=1024){
                int ixj=i^j;
                if(ixj>i){
                    unsigned long long a=keys[i], c=keys[ixj];
                    bool up=((i&k)==0);
                    if((a>c)==up){ keys[i]=c; keys[ixj]=a; }
                }
            }
            __syncthreads();
        }
    }

    unsigned long long key=keys[tid];
    int idx=(int)(key & 0xFFFFFFFFull);
    float score=sc[idx]*mk[idx];
    bool valid = score>0.5f;
    float xc=0.0f, yc=0.0f, ang=0.0f;
    if(!valid) score=0.0f;
    if(valid){
        int r=idx>>6, c=idx&63;
        const float* o=mori+(size_t)b*CMNT*NCELL+idx;
        int ai=0; float bv=o[0];
        for(int ch=1;ch<CMNT;ch++){ float v=o[(size_t)ch*NCELL]; if(v>bv){bv=v;ai=ch;} }
        const float* xo=mxo+(size_t)b*COFF*NCELL+idx;
        int xi=0; float bx=xo[0];
        for(int ch=1;ch<COFF;ch++){ float v=xo[(size_t)ch*NCELL]; if(v>bx){bx=v;xi=ch;} }
        const float* yo=myo+(size_t)b*COFF*NCELL+idx;
        int yi=0; float by=yo[0];
        for(int ch=1;ch<COFF;ch++){ float v=yo[(size_t)ch*NCELL]; if(v>by){by=v;yi=ch;} }
        ang=((float)ai*2.0f-89.0f)*0.017453292519943295f;
        xc=(float)c*8.0f+(float)xi;
        yc=(float)r*8.0f+(float)yi;
    }
    if(tid==0) s_nv=0;
    __syncthreads();                 // all keys reads done before aliased writes
    sx[tid]=xc; sy[tid]=yc; sa[tid]=ang; skeep[tid]=valid?1:0;
    atomicMax(&s_nv, valid?(tid+1):0);   // valid slots form a prefix after sort
    __syncthreads();
    int nv=s_nv;
    // sequential greedy NMS over valid prefix
    for(int i=0;i<nv;i++){
        if(skeep[i] && tid>i && skeep[tid]){
            float dx=sx[tid]-sx[i], dy=sy[tid]-sy[i];
            float d=sqrtf(dx*dx+dy*dy);
            float da=fabsf(sa[tid]-sa[i]);
            da=fminf(da, 6.2831853071795864f-da);
            if(d<16.0f && da<0.52359877559829887f) skeep[tid]=0;
        }
        __syncthreads();
    }
    float kf = skeep[tid]?1.0f:0.0f;
    float* om=out + MINUT_OFF + (size_t)b*KCAND*4 + (size_t)tid*4;
    om[0]=kf*xc; om[1]=kf*yc; om[2]=kf*ang; om[3]=kf*score;
    out[KEEP_OFF + (size_t)b*KCAND + tid]=kf;
}

// -------- finalize: enh_vis, mask*255, ori_field (mask-predicated argmax) --------
__global__ void finalize(const float* __restrict__ enh, const float* __restrict__ oriup,
                         float* __restrict__ out){
    int i=blockIdx.x*blockDim.x+threadIdx.x;
    if(i>=BNUM*NPIX) return;
    int b=i/NPIX, p=i%NPIX;
    float m=g_maskup[i];
    out[MASK_OFF+i]=m*255.0f;
    float emin=ord2f(g_emin[b]);
    float emax=ord2f(g_emax[b]);
    float e=enh[i]*m;
    out[ENH_OFF+i]=(e-emin)/(emax-emin+1e-8f)*255.0f;
    float of=0.0f;
    if(m!=0.0f){
        const float* o=oriup+(size_t)b*CORI*NPIX+p;
        int ai=0; float bv=o[0];
        for(int ch=1;ch<CORI;ch++){ float v=o[(size_t)ch*NPIX]; if(v>bv){bv=v;ai=ch;} }
        of=((float)ai*2.0f-90.0f)*0.017453292519943295f*m;
    }
    out[ORI_OFF+i]=of;
}

extern "C" void kernel_launch(void* const* d_in, const int* in_sizes, int n_in,
                              void* d_out, int out_size){
    const float* seg    =(const float*)d_in[0];
    const float* segup  =(const float*)d_in[1];
    const float* oriup  =(const float*)d_in[2];
    const float* enh    =(const float*)d_in[3];
    const float* mscore =(const float*)d_in[4];
    const float* mori   =(const float*)d_in[5];
    const float* mxo    =(const float*)d_in[6];
    const float* myo    =(const float*)d_in[7];
    float* out=(float*)d_out;

    int nSmall=(BNUM*NCELL+255)/256;
    int nBig  =(BNUM*NPIX +255)/256;

    small_erode<<<nSmall,256>>>(seg);    // includes minmax init
    small_dilate<<<nSmall,256>>>();

    up1_vmin<<<nBig,256>>>(segup);
    up2_hmin<<<nBig,256>>>();
    up3_vmax<<<nBig,256>>>();
    up4_hmax<<<nBig,256>>>();

    {
        dim3 g(64,BNUM);
        enh_minmax<<<g,256>>>(enh);
    }

    detect_nms<<<BNUM,1024>>>(mscore, mori, mxo, myo, out);
    finalize<<<nBig,256>>>(enh, oriup, out);
}